// round 1
// baseline (speedup 1.0000x reference)
#include <cuda_runtime.h>

// ---------------- static config ----------------
#define BB    16
#define HH    56
#define WW    56
#define CC    512
#define WSZ   7
#define SHIFT 3
#define NHEAD 16
#define HDIM  32
#define NTOK  49          // WSZ*WSZ
#define NWIN_PER_B 64     // (56/7)*(56/7)
#define NWIN  (BB*NWIN_PER_B)        // 1024
#define MROWS (NWIN*NTOK)            // 50176
#define SCALE 0.17677669529663687f   // 32^-0.5
#define LNEPS 1e-5f

// ---------------- scratch (device globals; no cudaMalloc allowed) ----------------
__device__ float g_xw[(size_t)MROWS * CC];   // LN+shifted windows, stream a (rescaled)
__device__ float g_yw[(size_t)MROWS * CC];   // LN+shifted windows, stream b (rescaler)
__device__ float g_q [(size_t)MROWS * CC];   // (win, head, n, d)
__device__ float g_k [(size_t)MROWS * CC];
__device__ float g_v [(size_t)MROWS * CC];
__device__ float g_att[(size_t)MROWS * CC];  // attention output, rows (win*49+n) x 512

// ================= Kernel 1: LayerNorm + roll(-3,-3) + window partition =================
// grid = (B*H*W, 2), block = 128 threads; each thread handles 4 channels (float4).
__global__ void ln_shift_window(const float* __restrict__ xa, const float* __restrict__ xb,
                                const float* __restrict__ ga, const float* __restrict__ ba,
                                const float* __restrict__ gb, const float* __restrict__ bb) {
    const int pix = blockIdx.x;            // b*3136 + h*56 + w
    const int sel = blockIdx.y;            // 0: stream a, 1: stream b
    const float* __restrict__ x  = sel ? xb : xa;
    const float* __restrict__ g  = sel ? gb : ga;
    const float* __restrict__ be = sel ? bb : ba;
    float* __restrict__ out      = sel ? g_yw : g_xw;

    const int t = threadIdx.x;             // 0..127
    const float4 v = ((const float4*)(x + (size_t)pix * CC))[t];

    float s  = v.x + v.y + v.z + v.w;
    float sq = v.x*v.x + v.y*v.y + v.z*v.z + v.w*v.w;
    #pragma unroll
    for (int o = 16; o > 0; o >>= 1) {
        s  += __shfl_down_sync(0xffffffffu, s,  o);
        sq += __shfl_down_sync(0xffffffffu, sq, o);
    }
    __shared__ float red[8];
    const int warp = t >> 5, lane = t & 31;
    if (lane == 0) { red[warp] = s; red[warp + 4] = sq; }
    __syncthreads();
    s  = red[0] + red[1] + red[2] + red[3];
    sq = red[4] + red[5] + red[6] + red[7];

    const float mean = s * (1.0f / CC);
    const float var  = sq * (1.0f / CC) - mean * mean;
    const float inv  = rsqrtf(var + LNEPS);

    const float4 gg = ((const float4*)g)[t];
    const float4 bt = ((const float4*)be)[t];
    float4 o;
    o.x = (v.x - mean) * inv * gg.x + bt.x;
    o.y = (v.y - mean) * inv * gg.y + bt.y;
    o.z = (v.z - mean) * inv * gg.z + bt.z;
    o.w = (v.w - mean) * inv * gg.w + bt.w;

    // destination: rolled coords -> window token
    const int b   = pix / (HH * WW);
    const int rem = pix % (HH * WW);
    const int h   = rem / WW, w = rem % WW;
    int hr = h - SHIFT; if (hr < 0) hr += HH;
    int wr = w - SHIFT; if (wr < 0) wr += WW;
    const int win = b * NWIN_PER_B + (hr / WSZ) * 8 + (wr / WSZ);
    const int n   = (hr % WSZ) * WSZ + (wr % WSZ);
    ((float4*)(out + ((size_t)(win * NTOK + n)) * CC))[t] = o;
}

// ================= Kernel 2: fp32 SGEMM 128x128x8 with fused epilogues =================
// C[r,c] = sum_k A[r,k] * Bw[k, coloff + c], A: MROWS x 512 (row-major, lda=512)
// mode 0: scatter to (win, head, n, d) layout (for q/k/v), val=(acc+bias[c])*scale
// mode 1: window-reverse + roll(+3,+3) into final output, val=acc+bias[c]
#define GBM 128
#define GBN 128
#define GBK 8
#define GTM 8
#define GTN 8

__global__ __launch_bounds__(256, 2)
void sgemm_epi(const float* __restrict__ A, const float* __restrict__ Bw,
               int ldb, int coloff,
               const float* __restrict__ bias, float scale,
               float* __restrict__ out, int mode) {
    __shared__ float As[GBK][GBM];
    __shared__ float Bs[GBK][GBN];

    const int bm  = blockIdx.y * GBM;
    const int bn  = blockIdx.x * GBN;
    const int tid = threadIdx.x;              // 0..255
    const int tx  = tid & 15;                 // col group
    const int ty  = tid >> 4;                 // row group

    const int arow  = tid >> 1;               // 0..127
    const int acol4 = (tid & 1) * 4;          // 0 or 4
    const int brow  = tid >> 5;               // 0..7
    const int bcol4 = (tid & 31) * 4;         // 0..124

    float acc[GTM][GTN];
    #pragma unroll
    for (int i = 0; i < GTM; i++)
        #pragma unroll
        for (int j = 0; j < GTN; j++) acc[i][j] = 0.0f;

    const float* __restrict__ Abase = A + (size_t)bm * CC;

    for (int k0 = 0; k0 < CC; k0 += GBK) {
        const float4 a4 = *(const float4*)(Abase + (size_t)arow * CC + k0 + acol4);
        As[acol4 + 0][arow] = a4.x;
        As[acol4 + 1][arow] = a4.y;
        As[acol4 + 2][arow] = a4.z;
        As[acol4 + 3][arow] = a4.w;
        const float4 b4 = *(const float4*)(Bw + (size_t)(k0 + brow) * ldb + coloff + bn + bcol4);
        *(float4*)&Bs[brow][bcol4] = b4;
        __syncthreads();

        #pragma unroll
        for (int kk = 0; kk < GBK; kk++) {
            float ar[GTM], br[GTN];
            #pragma unroll
            for (int i = 0; i < GTM; i++) ar[i] = As[kk][ty * GTM + i];
            #pragma unroll
            for (int j = 0; j < GTN; j++) br[j] = Bs[kk][tx * GTN + j];
            #pragma unroll
            for (int i = 0; i < GTM; i++)
                #pragma unroll
                for (int j = 0; j < GTN; j++) acc[i][j] += ar[i] * br[j];
        }
        __syncthreads();
    }

    #pragma unroll
    for (int i = 0; i < GTM; i++) {
        const int r   = bm + ty * GTM + i;
        const int win = r / NTOK;
        const int n   = r % NTOK;
        #pragma unroll
        for (int j = 0; j < GTN; j++) {
            const int c = bn + tx * GTN + j;
            const float val = (acc[i][j] + bias[c]) * scale;
            if (mode == 0) {
                const int head = c >> 5, d = c & 31;
                out[(((size_t)win * NHEAD + head) * NTOK + n) * HDIM + d] = val;
            } else {
                const int b  = win / NWIN_PER_B;
                const int lw = win % NWIN_PER_B;
                const int hr = (lw >> 3) * WSZ + n / WSZ;
                const int wr = (lw & 7)  * WSZ + n % WSZ;
                int h = hr + SHIFT; if (h >= HH) h -= HH;
                int w = wr + SHIFT; if (w >= WW) w -= WW;
                out[((size_t)b * (HH * WW) + h * WW + w) * CC + c] = val;
            }
        }
    }
}

// ================= Kernel 3: windowed attention =================
// grid = NWIN*NHEAD (16384), block = 256
__global__ __launch_bounds__(256)
void attn_kernel(const float* __restrict__ rpb_table) {
    const int unit = blockIdx.x;
    const int win  = unit >> 4;     // /16
    const int head = unit & 15;
    const int nw   = win & (NWIN_PER_B - 1);

    __shared__ float qs[NTOK][HDIM + 1];
    __shared__ float ks[NTOK][HDIM + 1];
    __shared__ float vs[NTOK][HDIM + 1];
    __shared__ float sc[NTOK][NTOK];
    __shared__ float rpb_s[169];
    __shared__ int   rid_s[NTOK];

    const int t = threadIdx.x;
    const float* __restrict__ qb = g_q + (size_t)unit * NTOK * HDIM;
    const float* __restrict__ kb = g_k + (size_t)unit * NTOK * HDIM;
    const float* __restrict__ vb = g_v + (size_t)unit * NTOK * HDIM;

    for (int e = t; e < NTOK * HDIM; e += 256) {
        const int n = e >> 5, d = e & 31;
        qs[n][d] = qb[e];
        ks[n][d] = kb[e];
        vs[n][d] = vb[e];
    }
    if (t < 169) rpb_s[t] = rpb_table[t * NHEAD + head];
    if (t < NTOK) {
        const int i = t / WSZ, j = t % WSZ;
        const int h = (nw >> 3) * WSZ + i;
        const int w = (nw & 7)  * WSZ + j;
        const int rh = (h < HH - WSZ) ? 0 : ((h < HH - SHIFT) ? 1 : 2);
        const int rw = (w < WW - WSZ) ? 0 : ((w < WW - SHIFT) ? 1 : 2);
        rid_s[t] = rh * 3 + rw;
    }
    __syncthreads();

    for (int e = t; e < NTOK * NTOK; e += 256) {
        const int n = e / NTOK, m = e % NTOK;
        float a = 0.0f;
        #pragma unroll
        for (int d = 0; d < HDIM; d++) a += qs[n][d] * ks[m][d];
        const int idx = (n / WSZ - m / WSZ + 6) * 13 + (n % WSZ - m % WSZ + 6);
        a += rpb_s[idx];
        if (rid_s[n] != rid_s[m]) a -= 100.0f;
        sc[n][m] = a;
    }
    __syncthreads();

    if (t < NTOK) {
        float mx = -1e30f;
        #pragma unroll
        for (int m = 0; m < NTOK; m++) mx = fmaxf(mx, sc[t][m]);
        float sum = 0.0f;
        #pragma unroll
        for (int m = 0; m < NTOK; m++) { const float ev = __expf(sc[t][m] - mx); sc[t][m] = ev; sum += ev; }
        const float inv = 1.0f / sum;
        #pragma unroll
        for (int m = 0; m < NTOK; m++) sc[t][m] *= inv;
    }
    __syncthreads();

    float* __restrict__ ob = g_att + (size_t)win * NTOK * CC + head * HDIM;
    for (int e = t; e < NTOK * HDIM; e += 256) {
        const int n = e >> 5, d = e & 31;
        float a = 0.0f;
        #pragma unroll
        for (int m = 0; m < NTOK; m++) a += sc[n][m] * vs[m][d];
        ob[(size_t)n * CC + d] = a;
    }
}

// ================= launch =================
extern "C" void kernel_launch(void* const* d_in, const int* in_sizes, int n_in,
                              void* d_out, int out_size) {
    const float* rescaled = (const float*)d_in[0];
    const float* rescaler = (const float*)d_in[1];
    const float* gamma_a  = (const float*)d_in[2];
    const float* beta_a   = (const float*)d_in[3];
    const float* gamma_b  = (const float*)d_in[4];
    const float* beta_b   = (const float*)d_in[5];
    const float* Wqkv_a   = (const float*)d_in[6];
    const float* bqkv_a   = (const float*)d_in[7];
    const float* Wqkv_b   = (const float*)d_in[8];
    const float* bqkv_b   = (const float*)d_in[9];
    const float* rpb      = (const float*)d_in[10];
    const float* Wproj    = (const float*)d_in[11];
    const float* bproj    = (const float*)d_in[12];
    float* out = (float*)d_out;

    float *p_xw, *p_yw, *p_q, *p_k, *p_v, *p_att;
    cudaGetSymbolAddress((void**)&p_xw,  g_xw);
    cudaGetSymbolAddress((void**)&p_yw,  g_yw);
    cudaGetSymbolAddress((void**)&p_q,   g_q);
    cudaGetSymbolAddress((void**)&p_k,   g_k);
    cudaGetSymbolAddress((void**)&p_v,   g_v);
    cudaGetSymbolAddress((void**)&p_att, g_att);

    // 1) LN + shift + window partition (both streams)
    ln_shift_window<<<dim3(BB * HH * WW, 2), 128>>>(rescaled, rescaler,
                                                    gamma_a, beta_a, gamma_b, beta_b);

    const dim3 ggrid(CC / GBN, MROWS / GBM);   // (4, 392)

    // 2) q from rescaler stream (cols 0:512 of Wqkv_b), scaled
    sgemm_epi<<<ggrid, 256>>>(p_yw, Wqkv_b, 3 * CC, 0,        bqkv_b + 0,      SCALE, p_q, 0);
    // 3) k from rescaled stream (cols 512:1024 of Wqkv_a)
    sgemm_epi<<<ggrid, 256>>>(p_xw, Wqkv_a, 3 * CC, CC,       bqkv_a + CC,     1.0f,  p_k, 0);
    // 4) v from rescaled stream (cols 1024:1536 of Wqkv_a)
    sgemm_epi<<<ggrid, 256>>>(p_xw, Wqkv_a, 3 * CC, 2 * CC,   bqkv_a + 2 * CC, 1.0f,  p_v, 0);

    // 5) attention per (window, head)
    attn_kernel<<<NWIN * NHEAD, 256>>>(rpb);

    // 6) output projection + window reverse + un-shift -> d_out
    sgemm_epi<<<ggrid, 256>>>(p_att, Wproj, CC, 0, bproj, 1.0f, out, 1);
}

// round 3
// speedup vs baseline: 1.6116x; 1.6116x over previous
#include <cuda_runtime.h>
#include <cstdint>

// ---------------- static config ----------------
#define BB    16
#define HH    56
#define WW    56
#define CC    512
#define WSZ   7
#define SHIFT 3
#define NHEAD 16
#define HDIM  32
#define NTOK  49
#define NWIN_PER_B 64
#define NWIN  (BB*NWIN_PER_B)        // 1024
#define MROWS (NWIN*NTOK)            // 50176
#define SCALE 0.17677669529663687f
#define LNEPS 1e-5f

// ---------------- scratch ----------------
__device__ float g_xw[(size_t)MROWS * CC];
__device__ float g_yw[(size_t)MROWS * CC];
__device__ float g_q [(size_t)MROWS * CC];
__device__ float g_k [(size_t)MROWS * CC];
__device__ float g_v [(size_t)MROWS * CC];
__device__ float g_att[(size_t)MROWS * CC];
__device__ float g_wt[4 * 512 * 512];        // pre-transposed weights [n][k]

__device__ __forceinline__ uint32_t f2tf32(float x) {
    uint32_t u;
    asm("cvt.rna.tf32.f32 %0, %1;" : "=r"(u) : "f"(x));
    return u;
}
__device__ __forceinline__ void mma_tf32(float* c, const uint32_t* a, const uint32_t* b) {
    asm volatile("mma.sync.aligned.m16n8k8.row.col.f32.tf32.tf32.f32 "
        "{%0,%1,%2,%3}, {%4,%5,%6,%7}, {%8,%9}, {%0,%1,%2,%3};"
        : "+f"(c[0]), "+f"(c[1]), "+f"(c[2]), "+f"(c[3])
        : "r"(a[0]), "r"(a[1]), "r"(a[2]), "r"(a[3]), "r"(b[0]), "r"(b[1]));
}

// ================= Kernel 1: LayerNorm + roll(-3,-3) + window partition =================
__global__ void ln_shift_window(const float* __restrict__ xa, const float* __restrict__ xb,
                                const float* __restrict__ ga, const float* __restrict__ ba,
                                const float* __restrict__ gb, const float* __restrict__ bb) {
    const int pix = blockIdx.x;
    const int sel = blockIdx.y;
    const float* __restrict__ x  = sel ? xb : xa;
    const float* __restrict__ g  = sel ? gb : ga;
    const float* __restrict__ be = sel ? bb : ba;
    float* __restrict__ out      = sel ? g_yw : g_xw;

    const int t = threadIdx.x;
    const float4 v = ((const float4*)(x + (size_t)pix * CC))[t];

    float s  = v.x + v.y + v.z + v.w;
    float sq = v.x*v.x + v.y*v.y + v.z*v.z + v.w*v.w;
    #pragma unroll
    for (int o = 16; o > 0; o >>= 1) {
        s  += __shfl_down_sync(0xffffffffu, s,  o);
        sq += __shfl_down_sync(0xffffffffu, sq, o);
    }
    __shared__ float red[8];
    const int warp = t >> 5, lane = t & 31;
    if (lane == 0) { red[warp] = s; red[warp + 4] = sq; }
    __syncthreads();
    s  = red[0] + red[1] + red[2] + red[3];
    sq = red[4] + red[5] + red[6] + red[7];

    const float mean = s * (1.0f / CC);
    const float var  = sq * (1.0f / CC) - mean * mean;
    const float inv  = rsqrtf(var + LNEPS);

    const float4 gg = ((const float4*)g)[t];
    const float4 bt = ((const float4*)be)[t];
    float4 o;
    o.x = (v.x - mean) * inv * gg.x + bt.x;
    o.y = (v.y - mean) * inv * gg.y + bt.y;
    o.z = (v.z - mean) * inv * gg.z + bt.z;
    o.w = (v.w - mean) * inv * gg.w + bt.w;

    const int b   = pix / (HH * WW);
    const int rem = pix % (HH * WW);
    const int h   = rem / WW, w = rem % WW;
    int hr = h - SHIFT; if (hr < 0) hr += HH;
    int wr = w - SHIFT; if (wr < 0) wr += WW;
    const int win = b * NWIN_PER_B + (hr / WSZ) * 8 + (wr / WSZ);
    const int n   = (hr % WSZ) * WSZ + (wr % WSZ);
    ((float4*)(out + ((size_t)(win * NTOK + n)) * CC))[t] = o;
}

// ================= Kernel 2: weight transpose (W[k][n] -> WT[n][k]) =================
__global__ void transpose_w(const float* __restrict__ Wqa, const float* __restrict__ Wqb,
                            const float* __restrict__ Wp) {
    __shared__ float tile[32][33];
    const int m = blockIdx.z;
    const float* src; int ld, off;
    if      (m == 0) { src = Wqb; ld = 1536; off = 0;    }
    else if (m == 1) { src = Wqa; ld = 1536; off = 512;  }
    else if (m == 2) { src = Wqa; ld = 1536; off = 1024; }
    else             { src = Wp;  ld = 512;  off = 0;    }
    float* dst = g_wt + (size_t)m * 512 * 512;
    const int n0 = blockIdx.x * 32, k0 = blockIdx.y * 32;
    const int tx = threadIdx.x, ty = threadIdx.y;
    #pragma unroll
    for (int i = 0; i < 32; i += 8)
        tile[ty + i][tx] = src[(size_t)(k0 + ty + i) * ld + off + n0 + tx];
    __syncthreads();
    #pragma unroll
    for (int i = 0; i < 32; i += 8)
        dst[(size_t)(n0 + ty + i) * 512 + k0 + tx] = tile[tx][ty + i];
}

// ================= Kernel 3: tf32 mma.sync GEMM 128x128x512 + fused epilogues =================
// C[r,c] = sum_k A[r,k] * WT[c,k]
// mode 0: scatter to (win, head, n, d), val=(acc+bias[c])*scale
// mode 1: window-reverse + roll(+3,+3), val=acc+bias[c]
#define LDS_ROW 36
#define STG_SZ  (128 * LDS_ROW)            // u32 elements per tensor stage
#define SMEM_DYN (4 * STG_SZ * 4)          // 2 tensors * 2 stages * 4 bytes = 73728

__global__ __launch_bounds__(256)
void gemm_tc(const float* __restrict__ A, const float* __restrict__ WT,
             const float* __restrict__ bias, float scale,
             float* __restrict__ out, int mode) {
    extern __shared__ uint32_t smem[];
    uint32_t* As = smem;                   // [2][128][36]
    uint32_t* Bs = smem + 2 * STG_SZ;      // [2][128][36]

    const int bm   = blockIdx.y * 128;
    const int bn   = blockIdx.x * 128;
    const int t    = threadIdx.x;
    const int wid  = t >> 5;
    const int lane = t & 31;
    const int gid  = lane >> 2;            // 0..7
    const int tig  = lane & 3;             // 0..3
    const int wm   = wid & 3;              // 0..3 -> 32 rows each
    const int wn   = wid >> 2;             // 0..1 -> 64 cols each

    // global load assignment: thread -> row r = t>>1, k-cols [(t&1)*16, +16)
    const int r  = t >> 1;
    const int cb = (t & 1) * 16;
    const float* __restrict__ Ap = A  + (size_t)(bm + r) * 512 + cb;
    const float* __restrict__ Bp = WT + (size_t)(bn + r) * 512 + cb;
    const int sts_off = r * LDS_ROW + cb;

    float acc[2][8][4];
    #pragma unroll
    for (int i = 0; i < 2; i++)
        #pragma unroll
        for (int j = 0; j < 8; j++)
            #pragma unroll
            for (int q = 0; q < 4; q++) acc[i][j][q] = 0.0f;

    float4 pa[4], pb[4];

    #define LDG_TILE(kt) do { \
        const float* Aq = Ap + (kt) * 32; \
        const float* Bq = Bp + (kt) * 32; \
        _Pragma("unroll") \
        for (int j = 0; j < 4; j++) { \
            pa[j] = *(const float4*)(Aq + j * 4); \
            pb[j] = *(const float4*)(Bq + j * 4); \
        } } while (0)

    #define STS_TILE(st) do { \
        uint32_t* Ad = As + (st) * STG_SZ + sts_off; \
        uint32_t* Bd = Bs + (st) * STG_SZ + sts_off; \
        _Pragma("unroll") \
        for (int j = 0; j < 4; j++) { \
            uint4 ua = { f2tf32(pa[j].x), f2tf32(pa[j].y), f2tf32(pa[j].z), f2tf32(pa[j].w) }; \
            uint4 ub = { f2tf32(pb[j].x), f2tf32(pb[j].y), f2tf32(pb[j].z), f2tf32(pb[j].w) }; \
            *(uint4*)(Ad + j * 4) = ua; \
            *(uint4*)(Bd + j * 4) = ub; \
        } } while (0)

    LDG_TILE(0);
    STS_TILE(0);

    for (int kt = 0; kt < 16; ++kt) {
        if (kt < 15) LDG_TILE(kt + 1);
        __syncthreads();
        if (kt < 15) STS_TILE((kt + 1) & 1);

        const uint32_t* Ab = As + (kt & 1) * STG_SZ + (wm * 32) * LDS_ROW;
        const uint32_t* Bb = Bs + (kt & 1) * STG_SZ + (wn * 64) * LDS_ROW;
        #pragma unroll
        for (int ks = 0; ks < 4; ++ks) {
            const int k0 = ks * 8;
            uint32_t af[2][4];
            #pragma unroll
            for (int i = 0; i < 2; i++) {
                const uint32_t* Ar = Ab + (i * 16 + gid) * LDS_ROW + k0 + tig;
                af[i][0] = Ar[0];
                af[i][1] = Ar[8 * LDS_ROW];
                af[i][2] = Ar[4];
                af[i][3] = Ar[8 * LDS_ROW + 4];
            }
            #pragma unroll
            for (int j = 0; j < 8; j++) {
                const uint32_t* Br = Bb + (j * 8 + gid) * LDS_ROW + k0 + tig;
                uint32_t bf[2] = { Br[0], Br[4] };
                mma_tf32(acc[0][j], af[0], bf);
                mma_tf32(acc[1][j], af[1], bf);
            }
        }
    }

    #undef LDG_TILE
    #undef STS_TILE

    // ---- epilogue ----
    const int row0 = bm + wm * 32;
    const int cw0  = bn + wn * 64;
    #pragma unroll
    for (int i = 0; i < 2; i++) {
        #pragma unroll
        for (int half = 0; half < 2; half++) {
            const int row = row0 + i * 16 + gid + half * 8;
            const int win = row / NTOK;
            const int n   = row % NTOK;
            float* rowbase;
            if (mode == 0) {
                rowbase = out + ((size_t)win * NHEAD * NTOK + n) * HDIM;  // + head*NTOK*HDIM + d
            } else {
                const int b  = win >> 6;
                const int lw = win & 63;
                const int hr = (lw >> 3) * WSZ + n / WSZ;
                const int wr = (lw & 7)  * WSZ + n % WSZ;
                int h = hr + SHIFT; if (h >= HH) h -= HH;
                int w = wr + SHIFT; if (w >= WW) w -= WW;
                rowbase = out + ((size_t)b * (HH * WW) + h * WW + w) * CC;
            }
            #pragma unroll
            for (int j = 0; j < 8; j++) {
                const int c = cw0 + j * 8 + tig * 2;
                const float2 bs = *(const float2*)(bias + c);
                float2 v;
                v.x = (acc[i][j][half * 2 + 0] + bs.x) * scale;
                v.y = (acc[i][j][half * 2 + 1] + bs.y) * scale;
                if (mode == 0) {
                    const int head = c >> 5, d = c & 31;
                    *(float2*)(rowbase + (size_t)head * NTOK * HDIM + d) = v;
                } else {
                    *(float2*)(rowbase + c) = v;
                }
            }
        }
    }
}

// ================= Kernel 4: windowed attention =================
__global__ __launch_bounds__(256)
void attn_kernel(const float* __restrict__ rpb_table) {
    const int unit = blockIdx.x;
    const int win  = unit >> 4;
    const int head = unit & 15;
    const int nw   = win & (NWIN_PER_B - 1);

    __shared__ float qs[NTOK][HDIM + 1];
    __shared__ float ks[NTOK][HDIM + 1];
    __shared__ float vs[NTOK][HDIM + 1];
    __shared__ float sc[NTOK][NTOK];
    __shared__ float rpb_s[169];
    __shared__ int   rid_s[NTOK];

    const int t = threadIdx.x;
    const float* __restrict__ qb = g_q + (size_t)unit * NTOK * HDIM;
    const float* __restrict__ kb = g_k + (size_t)unit * NTOK * HDIM;
    const float* __restrict__ vb = g_v + (size_t)unit * NTOK * HDIM;

    for (int e = t; e < NTOK * HDIM; e += 256) {
        const int n = e >> 5, d = e & 31;
        qs[n][d] = qb[e];
        ks[n][d] = kb[e];
        vs[n][d] = vb[e];
    }
    if (t < 169) rpb_s[t] = rpb_table[t * NHEAD + head];
    if (t < NTOK) {
        const int i = t / WSZ, j = t % WSZ;
        const int h = (nw >> 3) * WSZ + i;
        const int w = (nw & 7)  * WSZ + j;
        const int rh = (h < HH - WSZ) ? 0 : ((h < HH - SHIFT) ? 1 : 2);
        const int rw = (w < WW - WSZ) ? 0 : ((w < WW - SHIFT) ? 1 : 2);
        rid_s[t] = rh * 3 + rw;
    }
    __syncthreads();

    for (int e = t; e < NTOK * NTOK; e += 256) {
        const int n = e / NTOK, m = e % NTOK;
        float a = 0.0f;
        #pragma unroll
        for (int d = 0; d < HDIM; d++) a += qs[n][d] * ks[m][d];
        const int idx = (n / WSZ - m / WSZ + 6) * 13 + (n % WSZ - m % WSZ + 6);
        a += rpb_s[idx];
        if (rid_s[n] != rid_s[m]) a -= 100.0f;
        sc[n][m] = a;
    }
    __syncthreads();

    if (t < NTOK) {
        float mx = -1e30f;
        #pragma unroll
        for (int m = 0; m < NTOK; m++) mx = fmaxf(mx, sc[t][m]);
        float sum = 0.0f;
        #pragma unroll
        for (int m = 0; m < NTOK; m++) { const float ev = __expf(sc[t][m] - mx); sc[t][m] = ev; sum += ev; }
        const float inv = 1.0f / sum;
        #pragma unroll
        for (int m = 0; m < NTOK; m++) sc[t][m] *= inv;
    }
    __syncthreads();

    float* __restrict__ ob = g_att + (size_t)win * NTOK * CC + head * HDIM;
    for (int e = t; e < NTOK * HDIM; e += 256) {
        const int n = e >> 5, d = e & 31;
        float a = 0.0f;
        #pragma unroll
        for (int m = 0; m < NTOK; m++) a += sc[n][m] * vs[m][d];
        ob[(size_t)n * CC + d] = a;
    }
}

// ================= launch =================
extern "C" void kernel_launch(void* const* d_in, const int* in_sizes, int n_in,
                              void* d_out, int out_size) {
    const float* rescaled = (const float*)d_in[0];
    const float* rescaler = (const float*)d_in[1];
    const float* gamma_a  = (const float*)d_in[2];
    const float* beta_a   = (const float*)d_in[3];
    const float* gamma_b  = (const float*)d_in[4];
    const float* beta_b   = (const float*)d_in[5];
    const float* Wqkv_a   = (const float*)d_in[6];
    const float* bqkv_a   = (const float*)d_in[7];
    const float* Wqkv_b   = (const float*)d_in[8];
    const float* bqkv_b   = (const float*)d_in[9];
    const float* rpb      = (const float*)d_in[10];
    const float* Wproj    = (const float*)d_in[11];
    const float* bproj    = (const float*)d_in[12];
    float* out = (float*)d_out;

    float *p_xw, *p_yw, *p_q, *p_k, *p_v, *p_att, *p_wt;
    cudaGetSymbolAddress((void**)&p_xw,  g_xw);
    cudaGetSymbolAddress((void**)&p_yw,  g_yw);
    cudaGetSymbolAddress((void**)&p_q,   g_q);
    cudaGetSymbolAddress((void**)&p_k,   g_k);
    cudaGetSymbolAddress((void**)&p_v,   g_v);
    cudaGetSymbolAddress((void**)&p_att, g_att);
    cudaGetSymbolAddress((void**)&p_wt,  g_wt);

    cudaFuncSetAttribute(gemm_tc, cudaFuncAttributeMaxDynamicSharedMemorySize, SMEM_DYN);

    // 1) LN + shift + window partition
    ln_shift_window<<<dim3(BB * HH * WW, 2), 128>>>(rescaled, rescaler,
                                                    gamma_a, beta_a, gamma_b, beta_b);
    // 2) transpose the 4 weight slices
    transpose_w<<<dim3(16, 16, 4), dim3(32, 8)>>>(Wqkv_a, Wqkv_b, Wproj);

    const dim3 ggrid(4, MROWS / 128);   // (4, 392)

    // 3) q = (yw @ Wqkv_b[:, 0:512] + b) * SCALE
    gemm_tc<<<ggrid, 256, SMEM_DYN>>>(p_yw, p_wt + 0 * 262144, bqkv_b,          SCALE, p_q, 0);
    // 4) k = xw @ Wqkv_a[:, 512:1024] + b
    gemm_tc<<<ggrid, 256, SMEM_DYN>>>(p_xw, p_wt + 1 * 262144, bqkv_a + CC,     1.0f,  p_k, 0);
    // 5) v = xw @ Wqkv_a[:, 1024:1536] + b
    gemm_tc<<<ggrid, 256, SMEM_DYN>>>(p_xw, p_wt + 2 * 262144, bqkv_a + 2*CC,   1.0f,  p_v, 0);

    // 6) attention
    attn_kernel<<<NWIN * NHEAD, 256>>>(rpb);

    // 7) proj + window reverse + un-shift
    gemm_tc<<<ggrid, 256, SMEM_DYN>>>(p_att, p_wt + 3 * 262144, bproj, 1.0f, out, 1);
}

// round 4
// speedup vs baseline: 2.2737x; 1.4109x over previous
#include <cuda_runtime.h>
#include <cstdint>

// ---------------- static config ----------------
#define BB    16
#define HH    56
#define WW    56
#define CC    512
#define WSZ   7
#define SHIFT 3
#define NHEAD 16
#define HDIM  32
#define NTOK  49
#define NWIN_PER_B 64
#define NWIN  (BB*NWIN_PER_B)        // 1024
#define MROWS (NWIN*NTOK)            // 50176
#define SCALE 0.17677669529663687f
#define LNEPS 1e-5f

// ---------------- scratch ----------------
__device__ float g_xw[(size_t)MROWS * CC];
__device__ float g_yw[(size_t)MROWS * CC];
__device__ float g_q [(size_t)MROWS * CC];
__device__ float g_k [(size_t)MROWS * CC];
__device__ float g_v [(size_t)MROWS * CC];
__device__ float g_att[(size_t)MROWS * CC];
__device__ float g_wt[4 * 512 * 512];        // pre-transposed weights [n][k]

__device__ __forceinline__ uint32_t f2tf32(float x) {
    uint32_t u;
    asm("cvt.rna.tf32.f32 %0, %1;" : "=r"(u) : "f"(x));
    return u;
}
__device__ __forceinline__ void mma_tf32(float* c, const uint32_t* a, const uint32_t* b) {
    asm volatile("mma.sync.aligned.m16n8k8.row.col.f32.tf32.tf32.f32 "
        "{%0,%1,%2,%3}, {%4,%5,%6,%7}, {%8,%9}, {%0,%1,%2,%3};"
        : "+f"(c[0]), "+f"(c[1]), "+f"(c[2]), "+f"(c[3])
        : "r"(a[0]), "r"(a[1]), "r"(a[2]), "r"(a[3]), "r"(b[0]), "r"(b[1]));
}

// ================= Kernel 1: LayerNorm + roll(-3,-3) + window partition =================
__global__ void ln_shift_window(const float* __restrict__ xa, const float* __restrict__ xb,
                                const float* __restrict__ ga, const float* __restrict__ ba,
                                const float* __restrict__ gb, const float* __restrict__ bb) {
    const int pix = blockIdx.x;
    const int sel = blockIdx.y;
    const float* __restrict__ x  = sel ? xb : xa;
    const float* __restrict__ g  = sel ? gb : ga;
    const float* __restrict__ be = sel ? bb : ba;
    float* __restrict__ out      = sel ? g_yw : g_xw;

    const int t = threadIdx.x;
    const float4 v = ((const float4*)(x + (size_t)pix * CC))[t];

    float s  = v.x + v.y + v.z + v.w;
    float sq = v.x*v.x + v.y*v.y + v.z*v.z + v.w*v.w;
    #pragma unroll
    for (int o = 16; o > 0; o >>= 1) {
        s  += __shfl_down_sync(0xffffffffu, s,  o);
        sq += __shfl_down_sync(0xffffffffu, sq, o);
    }
    __shared__ float red[8];
    const int warp = t >> 5, lane = t & 31;
    if (lane == 0) { red[warp] = s; red[warp + 4] = sq; }
    __syncthreads();
    s  = red[0] + red[1] + red[2] + red[3];
    sq = red[4] + red[5] + red[6] + red[7];

    const float mean = s * (1.0f / CC);
    const float var  = sq * (1.0f / CC) - mean * mean;
    const float inv  = rsqrtf(var + LNEPS);

    const float4 gg = ((const float4*)g)[t];
    const float4 bt = ((const float4*)be)[t];
    float4 o;
    o.x = (v.x - mean) * inv * gg.x + bt.x;
    o.y = (v.y - mean) * inv * gg.y + bt.y;
    o.z = (v.z - mean) * inv * gg.z + bt.z;
    o.w = (v.w - mean) * inv * gg.w + bt.w;

    const int b   = pix / (HH * WW);
    const int rem = pix % (HH * WW);
    const int h   = rem / WW, w = rem % WW;
    int hr = h - SHIFT; if (hr < 0) hr += HH;
    int wr = w - SHIFT; if (wr < 0) wr += WW;
    const int win = b * NWIN_PER_B + (hr / WSZ) * 8 + (wr / WSZ);
    const int n   = (hr % WSZ) * WSZ + (wr % WSZ);
    ((float4*)(out + ((size_t)(win * NTOK + n)) * CC))[t] = o;
}

// ================= Kernel 2: weight transpose (W[k][n] -> WT[n][k]) =================
__global__ void transpose_w(const float* __restrict__ Wqa, const float* __restrict__ Wqb,
                            const float* __restrict__ Wp) {
    __shared__ float tile[32][33];
    const int m = blockIdx.z;
    const float* src; int ld, off;
    if      (m == 0) { src = Wqb; ld = 1536; off = 0;    }
    else if (m == 1) { src = Wqa; ld = 1536; off = 512;  }
    else if (m == 2) { src = Wqa; ld = 1536; off = 1024; }
    else             { src = Wp;  ld = 512;  off = 0;    }
    float* dst = g_wt + (size_t)m * 512 * 512;
    const int n0 = blockIdx.x * 32, k0 = blockIdx.y * 32;
    const int tx = threadIdx.x, ty = threadIdx.y;
    #pragma unroll
    for (int i = 0; i < 32; i += 8)
        tile[ty + i][tx] = src[(size_t)(k0 + ty + i) * ld + off + n0 + tx];
    __syncthreads();
    #pragma unroll
    for (int i = 0; i < 32; i += 8)
        dst[(size_t)(n0 + ty + i) * 512 + k0 + tx] = tile[tx][ty + i];
}

// ================= Kernel 3: tf32 mma.sync GEMM 128x128x512 + fused epilogues =================
#define LDS_ROW 36
#define STG_SZ  (128 * LDS_ROW)
#define SMEM_DYN (4 * STG_SZ * 4)          // 73728

__global__ __launch_bounds__(256, 2)
void gemm_tc(const float* __restrict__ A, const float* __restrict__ WT,
             const float* __restrict__ bias, float scale,
             float* __restrict__ out, int mode) {
    extern __shared__ uint32_t smem[];
    uint32_t* As = smem;                   // [2][128][36]
    uint32_t* Bs = smem + 2 * STG_SZ;      // [2][128][36]

    const int bm   = blockIdx.y * 128;
    const int bn   = blockIdx.x * 128;
    const int t    = threadIdx.x;
    const int wid  = t >> 5;
    const int lane = t & 31;
    const int gid  = lane >> 2;
    const int tig  = lane & 3;
    const int wm   = wid & 3;
    const int wn   = wid >> 2;

    const int r  = t >> 1;
    const int cb = (t & 1) * 16;
    const float* __restrict__ Ap = A  + (size_t)(bm + r) * 512 + cb;
    const float* __restrict__ Bp = WT + (size_t)(bn + r) * 512 + cb;
    const int sts_off = r * LDS_ROW + cb;

    float acc[2][8][4];
    #pragma unroll
    for (int i = 0; i < 2; i++)
        #pragma unroll
        for (int j = 0; j < 8; j++)
            #pragma unroll
            for (int q = 0; q < 4; q++) acc[i][j][q] = 0.0f;

    float4 pa[4], pb[4];

    #define LDG_TILE(kt) do { \
        const float* Aq = Ap + (kt) * 32; \
        const float* Bq = Bp + (kt) * 32; \
        _Pragma("unroll") \
        for (int j = 0; j < 4; j++) { \
            pa[j] = *(const float4*)(Aq + j * 4); \
            pb[j] = *(const float4*)(Bq + j * 4); \
        } } while (0)

    #define STS_TILE(st) do { \
        uint32_t* Ad = As + (st) * STG_SZ + sts_off; \
        uint32_t* Bd = Bs + (st) * STG_SZ + sts_off; \
        _Pragma("unroll") \
        for (int j = 0; j < 4; j++) { \
            uint4 ua = { f2tf32(pa[j].x), f2tf32(pa[j].y), f2tf32(pa[j].z), f2tf32(pa[j].w) }; \
            uint4 ub = { f2tf32(pb[j].x), f2tf32(pb[j].y), f2tf32(pb[j].z), f2tf32(pb[j].w) }; \
            *(uint4*)(Ad + j * 4) = ua; \
            *(uint4*)(Bd + j * 4) = ub; \
        } } while (0)

    LDG_TILE(0);
    STS_TILE(0);

    for (int kt = 0; kt < 16; ++kt) {
        if (kt < 15) LDG_TILE(kt + 1);
        __syncthreads();
        if (kt < 15) STS_TILE((kt + 1) & 1);

        const uint32_t* Ab = As + (kt & 1) * STG_SZ + (wm * 32) * LDS_ROW;
        const uint32_t* Bb = Bs + (kt & 1) * STG_SZ + (wn * 64) * LDS_ROW;
        #pragma unroll
        for (int ks = 0; ks < 4; ++ks) {
            const int k0 = ks * 8;
            uint32_t af[2][4];
            #pragma unroll
            for (int i = 0; i < 2; i++) {
                const uint32_t* Ar = Ab + (i * 16 + gid) * LDS_ROW + k0 + tig;
                af[i][0] = Ar[0];
                af[i][1] = Ar[8 * LDS_ROW];
                af[i][2] = Ar[4];
                af[i][3] = Ar[8 * LDS_ROW + 4];
            }
            #pragma unroll
            for (int j = 0; j < 8; j++) {
                const uint32_t* Br = Bb + (j * 8 + gid) * LDS_ROW + k0 + tig;
                uint32_t bf[2] = { Br[0], Br[4] };
                mma_tf32(acc[0][j], af[0], bf);
                mma_tf32(acc[1][j], af[1], bf);
            }
        }
    }

    #undef LDG_TILE
    #undef STS_TILE

    const int row0 = bm + wm * 32;
    const int cw0  = bn + wn * 64;
    #pragma unroll
    for (int i = 0; i < 2; i++) {
        #pragma unroll
        for (int half = 0; half < 2; half++) {
            const int row = row0 + i * 16 + gid + half * 8;
            const int win = row / NTOK;
            const int n   = row % NTOK;
            float* rowbase;
            if (mode == 0) {
                rowbase = out + ((size_t)win * NHEAD * NTOK + n) * HDIM;
            } else {
                const int b  = win >> 6;
                const int lw = win & 63;
                const int hr = (lw >> 3) * WSZ + n / WSZ;
                const int wr = (lw & 7)  * WSZ + n % WSZ;
                int h = hr + SHIFT; if (h >= HH) h -= HH;
                int w = wr + SHIFT; if (w >= WW) w -= WW;
                rowbase = out + ((size_t)b * (HH * WW) + h * WW + w) * CC;
            }
            #pragma unroll
            for (int j = 0; j < 8; j++) {
                const int c = cw0 + j * 8 + tig * 2;
                const float2 bs = *(const float2*)(bias + c);
                float2 v;
                v.x = (acc[i][j][half * 2 + 0] + bs.x) * scale;
                v.y = (acc[i][j][half * 2 + 1] + bs.y) * scale;
                if (mode == 0) {
                    const int head = c >> 5, d = c & 31;
                    *(float2*)(rowbase + (size_t)head * NTOK * HDIM + d) = v;
                } else {
                    *(float2*)(rowbase + c) = v;
                }
            }
        }
    }
}

// ================= Kernel 4: tensor-core windowed attention =================
// one block per (window, head); 4 warps; 64x64 padded score tile via m16n8k8 tf32
#define VT_ROW 72
#define PS_ROW 76

__global__ __launch_bounds__(128)
void attn_mma(const float* __restrict__ rpb_table) {
    const int unit = blockIdx.x;
    const int win  = unit >> 4;
    const int head = unit & 15;
    const int nw   = win & (NWIN_PER_B - 1);

    __shared__ uint32_t Qs[64][36];
    __shared__ uint32_t Ks[64][36];
    __shared__ uint32_t Vt[32][VT_ROW];   // Vt[d][m]
    __shared__ uint32_t Ps[64][PS_ROW];
    __shared__ float rpb_s[169];
    __shared__ int   rid_s[NTOK];

    const int t    = threadIdx.x;
    const int wid  = t >> 5;
    const int lane = t & 31;
    const int gid  = lane >> 2;
    const int tig  = lane & 3;
    const int r0   = wid * 16;

    const float* __restrict__ qb = g_q + (size_t)unit * NTOK * HDIM;
    const float* __restrict__ kb = g_k + (size_t)unit * NTOK * HDIM;
    const float* __restrict__ vb = g_v + (size_t)unit * NTOK * HDIM;

    for (int e = t; e < NTOK * HDIM; e += 128) {
        const int n = e >> 5, d = e & 31;
        Qs[n][d] = f2tf32(qb[e]);
        Ks[n][d] = f2tf32(kb[e]);
        Vt[d][n] = f2tf32(vb[e]);
    }
    // zero padding: rows 49..63 of Qs/Ks (cols 0..31), cols 49..63 of Vt
    for (int e = t; e < 15 * 32; e += 128) {
        const int n = 49 + (e >> 5), d = e & 31;
        Qs[n][d] = 0u;
        Ks[n][d] = 0u;
        Vt[d][49 + (e & 15)] = 0u;   // covers m 49..63 (each twice; harmless)
    }
    for (int e = t; e < 169; e += 128) rpb_s[e] = rpb_table[e * NHEAD + head];
    if (t < NTOK) {
        const int i = t / WSZ, j = t % WSZ;
        const int h = (nw >> 3) * WSZ + i;
        const int w = (nw & 7)  * WSZ + j;
        const int rh = (h < HH - WSZ) ? 0 : ((h < HH - SHIFT) ? 1 : 2);
        const int rw = (w < WW - WSZ) ? 0 : ((w < WW - SHIFT) ? 1 : 2);
        rid_s[t] = rh * 3 + rw;
    }
    __syncthreads();

    // ---- QK^T: warp computes rows [r0, r0+16) x cols [0,64) ----
    float accs[8][4];
    #pragma unroll
    for (int j = 0; j < 8; j++)
        #pragma unroll
        for (int q = 0; q < 4; q++) accs[j][q] = 0.0f;

    #pragma unroll
    for (int ks = 0; ks < 4; ++ks) {
        const int k0 = ks * 8;
        uint32_t af[4];
        af[0] = Qs[r0 + gid][k0 + tig];
        af[1] = Qs[r0 + gid + 8][k0 + tig];
        af[2] = Qs[r0 + gid][k0 + tig + 4];
        af[3] = Qs[r0 + gid + 8][k0 + tig + 4];
        #pragma unroll
        for (int nt = 0; nt < 8; nt++) {
            uint32_t bf[2] = { Ks[nt * 8 + gid][k0 + tig], Ks[nt * 8 + gid][k0 + tig + 4] };
            mma_tf32(accs[nt], af, bf);
        }
    }

    // ---- rpb + shift-mask (in fragment) ----
    const int rowA = r0 + gid;       // q = 0,1
    const int rowB = r0 + gid + 8;   // q = 2,3
    #pragma unroll
    for (int nt = 0; nt < 8; nt++) {
        #pragma unroll
        for (int q = 0; q < 4; q++) {
            const int row = (q >= 2) ? rowB : rowA;
            const int col = nt * 8 + tig * 2 + (q & 1);
            if (col >= NTOK) {
                accs[nt][q] = -1e30f;
            } else if (row < NTOK) {
                const int idx = (row / WSZ - col / WSZ + 6) * 13 + (row % WSZ - col % WSZ + 6);
                float a = accs[nt][q] + rpb_s[idx];
                if (rid_s[row] != rid_s[col]) a -= 100.0f;
                accs[nt][q] = a;
            }
        }
    }

    // ---- softmax over cols (per row; row is spread over the 4 tig lanes) ----
    float mx0 = -1e30f, mx1 = -1e30f;
    #pragma unroll
    for (int nt = 0; nt < 8; nt++) {
        mx0 = fmaxf(mx0, fmaxf(accs[nt][0], accs[nt][1]));
        mx1 = fmaxf(mx1, fmaxf(accs[nt][2], accs[nt][3]));
    }
    #pragma unroll
    for (int o = 1; o < 4; o <<= 1) {
        mx0 = fmaxf(mx0, __shfl_xor_sync(0xffffffffu, mx0, o));
        mx1 = fmaxf(mx1, __shfl_xor_sync(0xffffffffu, mx1, o));
    }
    float s0 = 0.0f, s1 = 0.0f;
    #pragma unroll
    for (int nt = 0; nt < 8; nt++) {
        float e0 = __expf(accs[nt][0] - mx0); accs[nt][0] = e0; s0 += e0;
        float e1 = __expf(accs[nt][1] - mx0); accs[nt][1] = e1; s0 += e1;
        float e2 = __expf(accs[nt][2] - mx1); accs[nt][2] = e2; s1 += e2;
        float e3 = __expf(accs[nt][3] - mx1); accs[nt][3] = e3; s1 += e3;
    }
    #pragma unroll
    for (int o = 1; o < 4; o <<= 1) {
        s0 += __shfl_xor_sync(0xffffffffu, s0, o);
        s1 += __shfl_xor_sync(0xffffffffu, s1, o);
    }
    const float i0 = 1.0f / s0, i1 = 1.0f / s1;

    // ---- store P (tf32) ----
    #pragma unroll
    for (int nt = 0; nt < 8; nt++) {
        const int col = nt * 8 + tig * 2;
        Ps[rowA][col]     = f2tf32(accs[nt][0] * i0);
        Ps[rowA][col + 1] = f2tf32(accs[nt][1] * i0);
        Ps[rowB][col]     = f2tf32(accs[nt][2] * i1);
        Ps[rowB][col + 1] = f2tf32(accs[nt][3] * i1);
    }
    __syncwarp();

    // ---- PV: rows [r0, r0+16) x d [0,32), k over 64 ----
    float acco[4][4];
    #pragma unroll
    for (int j = 0; j < 4; j++)
        #pragma unroll
        for (int q = 0; q < 4; q++) acco[j][q] = 0.0f;

    #pragma unroll
    for (int ks = 0; ks < 8; ++ks) {
        const int k0 = ks * 8;
        uint32_t af[4];
        af[0] = Ps[rowA][k0 + tig];
        af[1] = Ps[rowB][k0 + tig];
        af[2] = Ps[rowA][k0 + tig + 4];
        af[3] = Ps[rowB][k0 + tig + 4];
        #pragma unroll
        for (int nt = 0; nt < 4; nt++) {
            uint32_t bf[2] = { Vt[nt * 8 + gid][k0 + tig], Vt[nt * 8 + gid][k0 + tig + 4] };
            mma_tf32(acco[nt], af, bf);
        }
    }

    // ---- store output ----
    float* __restrict__ ob = g_att + (size_t)win * NTOK * CC + head * HDIM;
    #pragma unroll
    for (int h = 0; h < 2; h++) {
        const int row = r0 + gid + h * 8;
        if (row < NTOK) {
            #pragma unroll
            for (int nt = 0; nt < 4; nt++) {
                const int d = nt * 8 + tig * 2;
                float2 v = { acco[nt][h * 2], acco[nt][h * 2 + 1] };
                *(float2*)(ob + (size_t)row * CC + d) = v;
            }
        }
    }
}

// ================= launch =================
extern "C" void kernel_launch(void* const* d_in, const int* in_sizes, int n_in,
                              void* d_out, int out_size) {
    const float* rescaled = (const float*)d_in[0];
    const float* rescaler = (const float*)d_in[1];
    const float* gamma_a  = (const float*)d_in[2];
    const float* beta_a   = (const float*)d_in[3];
    const float* gamma_b  = (const float*)d_in[4];
    const float* beta_b   = (const float*)d_in[5];
    const float* Wqkv_a   = (const float*)d_in[6];
    const float* bqkv_a   = (const float*)d_in[7];
    const float* Wqkv_b   = (const float*)d_in[8];
    const float* bqkv_b   = (const float*)d_in[9];
    const float* rpb      = (const float*)d_in[10];
    const float* Wproj    = (const float*)d_in[11];
    const float* bproj    = (const float*)d_in[12];
    float* out = (float*)d_out;

    float *p_xw, *p_yw, *p_q, *p_k, *p_v, *p_att, *p_wt;
    cudaGetSymbolAddress((void**)&p_xw,  g_xw);
    cudaGetSymbolAddress((void**)&p_yw,  g_yw);
    cudaGetSymbolAddress((void**)&p_q,   g_q);
    cudaGetSymbolAddress((void**)&p_k,   g_k);
    cudaGetSymbolAddress((void**)&p_v,   g_v);
    cudaGetSymbolAddress((void**)&p_att, g_att);
    cudaGetSymbolAddress((void**)&p_wt,  g_wt);

    cudaFuncSetAttribute(gemm_tc, cudaFuncAttributeMaxDynamicSharedMemorySize, SMEM_DYN);

    ln_shift_window<<<dim3(BB * HH * WW, 2), 128>>>(rescaled, rescaler,
                                                    gamma_a, beta_a, gamma_b, beta_b);
    transpose_w<<<dim3(16, 16, 4), dim3(32, 8)>>>(Wqkv_a, Wqkv_b, Wproj);

    const dim3 ggrid(4, MROWS / 128);

    gemm_tc<<<ggrid, 256, SMEM_DYN>>>(p_yw, p_wt + 0 * 262144, bqkv_b,          SCALE, p_q, 0);
    gemm_tc<<<ggrid, 256, SMEM_DYN>>>(p_xw, p_wt + 1 * 262144, bqkv_a + CC,     1.0f,  p_k, 0);
    gemm_tc<<<ggrid, 256, SMEM_DYN>>>(p_xw, p_wt + 2 * 262144, bqkv_a + 2*CC,   1.0f,  p_v, 0);

    attn_mma<<<NWIN * NHEAD, 128>>>(rpb);

    gemm_tc<<<ggrid, 256, SMEM_DYN>>>(p_att, p_wt + 3 * 262144, bproj, 1.0f, out, 1);
}

// round 6
// speedup vs baseline: 2.5633x; 1.1274x over previous
#include <cuda_runtime.h>
#include <cstdint>

// ---------------- static config ----------------
#define BB    16
#define HH    56
#define WW    56
#define CC    512
#define WSZ   7
#define SHIFT 3
#define NHEAD 16
#define HDIM  32
#define NTOK  49
#define NWIN_PER_B 64
#define NWIN  (BB*NWIN_PER_B)        // 1024
#define MROWS (NWIN*NTOK)            // 50176
#define SCALE 0.17677669529663687f
#define LNEPS 1e-5f

// ---------------- scratch ----------------
__device__ float g_xw[(size_t)MROWS * CC];
__device__ float g_yw[(size_t)MROWS * CC];
__device__ float g_q [(size_t)MROWS * CC];
__device__ float g_k [(size_t)MROWS * CC];
__device__ float g_v [(size_t)MROWS * CC];
__device__ float g_att[(size_t)MROWS * CC];
__device__ float g_wt[4 * 512 * 512];        // pre-transposed, tf32-rounded weights [n][k]

__device__ __forceinline__ uint32_t f2tf32(float x) {
    uint32_t u;
    asm("cvt.rna.tf32.f32 %0, %1;" : "=r"(u) : "f"(x));
    return u;
}
__device__ __forceinline__ float rnd_tf32(float x) {
    return __uint_as_float(f2tf32(x));
}
__device__ __forceinline__ void mma_tf32(float* c, const uint32_t* a, const uint32_t* b) {
    asm volatile("mma.sync.aligned.m16n8k8.row.col.f32.tf32.tf32.f32 "
        "{%0,%1,%2,%3}, {%4,%5,%6,%7}, {%8,%9}, {%0,%1,%2,%3};"
        : "+f"(c[0]), "+f"(c[1]), "+f"(c[2]), "+f"(c[3])
        : "r"(a[0]), "r"(a[1]), "r"(a[2]), "r"(a[3]), "r"(b[0]), "r"(b[1]));
}
__device__ __forceinline__ uint32_t smem_u32(const void* p) {
    uint32_t a;
    asm("{ .reg .u64 t; cvta.to.shared.u64 t, %1; cvt.u32.u64 %0, t; }" : "=r"(a) : "l"(p));
    return a;
}
#define LDSM4(r, addr) \
    asm volatile("ldmatrix.sync.aligned.m8n8.x4.shared.b16 {%0,%1,%2,%3}, [%4];" \
        : "=r"((r)[0]), "=r"((r)[1]), "=r"((r)[2]), "=r"((r)[3]) : "r"(addr))
#define CP16(sa, gp) \
    asm volatile("cp.async.cg.shared.global [%0], [%1], 16;" :: "r"(sa), "l"(gp))
#define CP_COMMIT() asm volatile("cp.async.commit_group;" ::: "memory")

// ================= Kernel 1: LayerNorm + roll(-3,-3) + window partition (tf32-rounded) ====
__global__ void ln_shift_window(const float* __restrict__ xa, const float* __restrict__ xb,
                                const float* __restrict__ ga, const float* __restrict__ ba,
                                const float* __restrict__ gb, const float* __restrict__ bb) {
    const int pix = blockIdx.x;
    const int sel = blockIdx.y;
    const float* __restrict__ x  = sel ? xb : xa;
    const float* __restrict__ g  = sel ? gb : ga;
    const float* __restrict__ be = sel ? bb : ba;
    float* __restrict__ out      = sel ? g_yw : g_xw;

    const int t = threadIdx.x;
    const float4 v = ((const float4*)(x + (size_t)pix * CC))[t];

    float s  = v.x + v.y + v.z + v.w;
    float sq = v.x*v.x + v.y*v.y + v.z*v.z + v.w*v.w;
    #pragma unroll
    for (int o = 16; o > 0; o >>= 1) {
        s  += __shfl_down_sync(0xffffffffu, s,  o);
        sq += __shfl_down_sync(0xffffffffu, sq, o);
    }
    __shared__ float red[8];
    const int warp = t >> 5, lane = t & 31;
    if (lane == 0) { red[warp] = s; red[warp + 4] = sq; }
    __syncthreads();
    s  = red[0] + red[1] + red[2] + red[3];
    sq = red[4] + red[5] + red[6] + red[7];

    const float mean = s * (1.0f / CC);
    const float var  = sq * (1.0f / CC) - mean * mean;
    const float inv  = rsqrtf(var + LNEPS);

    const float4 gg = ((const float4*)g)[t];
    const float4 bt = ((const float4*)be)[t];
    float4 o;
    o.x = rnd_tf32((v.x - mean) * inv * gg.x + bt.x);
    o.y = rnd_tf32((v.y - mean) * inv * gg.y + bt.y);
    o.z = rnd_tf32((v.z - mean) * inv * gg.z + bt.z);
    o.w = rnd_tf32((v.w - mean) * inv * gg.w + bt.w);

    const int b   = pix / (HH * WW);
    const int rem = pix % (HH * WW);
    const int h   = rem / WW, w = rem % WW;
    int hr = h - SHIFT; if (hr < 0) hr += HH;
    int wr = w - SHIFT; if (wr < 0) wr += WW;
    const int win = b * NWIN_PER_B + (hr / WSZ) * 8 + (wr / WSZ);
    const int n   = (hr % WSZ) * WSZ + (wr % WSZ);
    ((float4*)(out + ((size_t)(win * NTOK + n)) * CC))[t] = o;
}

// ================= Kernel 2: weight transpose + tf32 round =================
__global__ void transpose_w(const float* __restrict__ Wqa, const float* __restrict__ Wqb,
                            const float* __restrict__ Wp) {
    __shared__ float tile[32][33];
    const int m = blockIdx.z;
    const float* src; int ld, off;
    if      (m == 0) { src = Wqb; ld = 1536; off = 0;    }
    else if (m == 1) { src = Wqa; ld = 1536; off = 512;  }
    else if (m == 2) { src = Wqa; ld = 1536; off = 1024; }
    else             { src = Wp;  ld = 512;  off = 0;    }
    float* dst = g_wt + (size_t)m * 512 * 512;
    const int n0 = blockIdx.x * 32, k0 = blockIdx.y * 32;
    const int tx = threadIdx.x, ty = threadIdx.y;
    #pragma unroll
    for (int i = 0; i < 32; i += 8)
        tile[ty + i][tx] = src[(size_t)(k0 + ty + i) * ld + off + n0 + tx];
    __syncthreads();
    #pragma unroll
    for (int i = 0; i < 32; i += 8)
        dst[(size_t)(n0 + ty + i) * 512 + k0 + tx] = rnd_tf32(tile[tx][ty + i]);
}

// ================= Kernel 3: tf32 mma.sync GEMM, cp.async 3-stage + ldmatrix =============
#define LDS_ROW 36
#define STG_SZ  (128 * LDS_ROW)                   // u32 per tensor-stage (4608)
#define STG_B   (STG_SZ * 4)                      // bytes (18432)
#define SMEM_DYN (6 * STG_B)                      // 110592

__global__ __launch_bounds__(256, 2)
void gemm_tc(const float* __restrict__ A, const float* __restrict__ WT,
             const float* __restrict__ bias, float scale,
             float* __restrict__ out, int mode) {
    extern __shared__ uint32_t smem[];

    const int bm   = blockIdx.y * 128;
    const int bn   = blockIdx.x * 128;
    const int t    = threadIdx.x;
    const int wid  = t >> 5;
    const int lane = t & 31;
    const int gid  = lane >> 2;
    const int tig  = lane & 3;
    const int wm   = wid & 3;
    const int wn   = wid >> 2;

    const uint32_t sBase = smem_u32(smem);         // A stages at +0, B stages at +3*STG_B

    // ---- cp.async assignment: row r = t>>1, k-cols [(t&1)*16, +16) as 4x16B ----
    const int r  = t >> 1;
    const int cb = (t & 1) * 16;
    const float* __restrict__ Ap = A  + (size_t)(bm + r) * 512 + cb;
    const float* __restrict__ Bp = WT + (size_t)(bn + r) * 512 + cb;
    const uint32_t stsByte = (uint32_t)(r * LDS_ROW + cb) * 4;

    #define PREFETCH(kt, st) do { \
        const uint32_t aDst = sBase + (st) * STG_B + stsByte; \
        const uint32_t bDst = sBase + 3 * STG_B + (st) * STG_B + stsByte; \
        const float* Aq = Ap + (kt) * 32; \
        const float* Bq = Bp + (kt) * 32; \
        _Pragma("unroll") \
        for (int j = 0; j < 4; j++) { \
            CP16(aDst + j * 16, Aq + j * 4); \
            CP16(bDst + j * 16, Bq + j * 4); \
        } \
        CP_COMMIT(); } while (0)

    // ---- ldmatrix per-lane offsets ----
    const int mat  = lane >> 3;
    const int rInM = lane & 7;
    // A quadrants: m0 (rows+0, k+0), m1 (rows+8, k+0), m2 (rows+0, k+4), m3 (rows+8, k+4)
    const uint32_t aOffL = (uint32_t)((wm * 32 + rInM + (mat & 1) * 8) * LDS_ROW
                                      + (mat >> 1) * 4) * 4;
    // B quadrants: m0 (n+0, k+0), m1 (n+0, k+4), m2 (n+8, k+0), m3 (n+8, k+4)
    const uint32_t bOffL = (uint32_t)((wn * 64 + rInM + (mat >> 1) * 8) * LDS_ROW
                                      + (mat & 1) * 4) * 4;

    float acc[2][8][4];
    #pragma unroll
    for (int i = 0; i < 2; i++)
        #pragma unroll
        for (int j = 0; j < 8; j++)
            #pragma unroll
            for (int q = 0; q < 4; q++) acc[i][j][q] = 0.0f;

    PREFETCH(0, 0);
    PREFETCH(1, 1);

    int st = 0;
    for (int kt = 0; kt < 16; ++kt) {
        if (kt + 1 < 16) {
            asm volatile("cp.async.wait_group 1;" ::: "memory");
        } else {
            asm volatile("cp.async.wait_group 0;" ::: "memory");
        }
        __syncthreads();
        // prefetch AFTER the barrier: stage (kt+2)%3 == stage of tile kt-1,
        // whose readers are guaranteed past the barrier above.
        if (kt + 2 < 16) {
            const int st2 = (st + 2 >= 3) ? st - 1 : st + 2;
            PREFETCH(kt + 2, st2);
        }

        const uint32_t aB = sBase + st * STG_B + aOffL;
        const uint32_t bB = sBase + 3 * STG_B + st * STG_B + bOffL;
        #pragma unroll
        for (int ks = 0; ks < 4; ++ks) {
            const uint32_t kb = ks * 32;
            uint32_t a0[4], a1[4];
            LDSM4(a0, aB + kb);
            LDSM4(a1, aB + 16 * LDS_ROW * 4 + kb);
            #pragma unroll
            for (int jp = 0; jp < 4; ++jp) {
                uint32_t bq[4];
                LDSM4(bq, bB + jp * 16 * LDS_ROW * 4 + kb);
                mma_tf32(acc[0][2*jp],     a0, bq);
                mma_tf32(acc[0][2*jp + 1], a0, bq + 2);
                mma_tf32(acc[1][2*jp],     a1, bq);
                mma_tf32(acc[1][2*jp + 1], a1, bq + 2);
            }
        }
        st = (st + 1 == 3) ? 0 : st + 1;
    }
    #undef PREFETCH

    // ---- epilogue ----
    const int row0 = bm + wm * 32;
    const int cw0  = bn + wn * 64;
    #pragma unroll
    for (int i = 0; i < 2; i++) {
        #pragma unroll
        for (int half = 0; half < 2; half++) {
            const int row = row0 + i * 16 + gid + half * 8;
            const int win = row / NTOK;
            const int n   = row % NTOK;
            float* rowbase;
            if (mode == 0) {
                rowbase = out + ((size_t)win * NHEAD * NTOK + n) * HDIM;
            } else {
                const int b  = win >> 6;
                const int lw = win & 63;
                const int hr = (lw >> 3) * WSZ + n / WSZ;
                const int wr = (lw & 7)  * WSZ + n % WSZ;
                int h = hr + SHIFT; if (h >= HH) h -= HH;
                int w = wr + SHIFT; if (w >= WW) w -= WW;
                rowbase = out + ((size_t)b * (HH * WW) + h * WW + w) * CC;
            }
            #pragma unroll
            for (int j = 0; j < 8; j++) {
                const int c = cw0 + j * 8 + tig * 2;
                const float2 bs = *(const float2*)(bias + c);
                float2 v;
                v.x = (acc[i][j][half * 2 + 0] + bs.x) * scale;
                v.y = (acc[i][j][half * 2 + 1] + bs.y) * scale;
                if (mode == 0) {
                    const int head = c >> 5, d = c & 31;
                    *(float2*)(rowbase + (size_t)head * NTOK * HDIM + d) = v;
                } else {
                    *(float2*)(rowbase + c) = v;
                }
            }
        }
    }
}

// ================= Kernel 4: tensor-core windowed attention =================
#define VT_ROW 72
#define PS_ROW 76

__global__ __launch_bounds__(128)
void attn_mma(const float* __restrict__ rpb_table) {
    const int unit = blockIdx.x;
    const int win  = unit >> 4;
    const int head = unit & 15;
    const int nw   = win & (NWIN_PER_B - 1);

    __shared__ uint32_t Qs[64][36];
    __shared__ uint32_t Ks[64][36];
    __shared__ uint32_t Vt[32][VT_ROW];   // Vt[d][m]
    __shared__ uint32_t Ps[64][PS_ROW];
    __shared__ float rpb_s[169];
    __shared__ int   rid_s[NTOK];

    const int t    = threadIdx.x;
    const int wid  = t >> 5;
    const int lane = t & 31;
    const int gid  = lane >> 2;
    const int tig  = lane & 3;
    const int r0   = wid * 16;

    const float* __restrict__ qb = g_q + (size_t)unit * NTOK * HDIM;
    const float* __restrict__ kb = g_k + (size_t)unit * NTOK * HDIM;
    const float* __restrict__ vb = g_v + (size_t)unit * NTOK * HDIM;

    for (int e = t; e < NTOK * HDIM; e += 128) {
        const int n = e >> 5, d = e & 31;
        Qs[n][d] = f2tf32(qb[e]);
        Ks[n][d] = f2tf32(kb[e]);
        Vt[d][n] = f2tf32(vb[e]);
    }
    for (int e = t; e < 15 * 32; e += 128) {
        const int n = 49 + (e >> 5), d = e & 31;
        Qs[n][d] = 0u;
        Ks[n][d] = 0u;
        Vt[d][49 + (e & 15)] = 0u;
    }
    for (int e = t; e < 169; e += 128) rpb_s[e] = rpb_table[e * NHEAD + head];
    if (t < NTOK) {
        const int i = t / WSZ, j = t % WSZ;
        const int h = (nw >> 3) * WSZ + i;
        const int w = (nw & 7)  * WSZ + j;
        const int rh = (h < HH - WSZ) ? 0 : ((h < HH - SHIFT) ? 1 : 2);
        const int rw = (w < WW - WSZ) ? 0 : ((w < WW - SHIFT) ? 1 : 2);
        rid_s[t] = rh * 3 + rw;
    }
    __syncthreads();

    float accs[8][4];
    #pragma unroll
    for (int j = 0; j < 8; j++)
        #pragma unroll
        for (int q = 0; q < 4; q++) accs[j][q] = 0.0f;

    #pragma unroll
    for (int ks = 0; ks < 4; ++ks) {
        const int k0 = ks * 8;
        uint32_t af[4];
        af[0] = Qs[r0 + gid][k0 + tig];
        af[1] = Qs[r0 + gid + 8][k0 + tig];
        af[2] = Qs[r0 + gid][k0 + tig + 4];
        af[3] = Qs[r0 + gid + 8][k0 + tig + 4];
        #pragma unroll
        for (int nt = 0; nt < 8; nt++) {
            uint32_t bf[2] = { Ks[nt * 8 + gid][k0 + tig], Ks[nt * 8 + gid][k0 + tig + 4] };
            mma_tf32(accs[nt], af, bf);
        }
    }

    const int rowA = r0 + gid;
    const int rowB = r0 + gid + 8;
    #pragma unroll
    for (int nt = 0; nt < 8; nt++) {
        #pragma unroll
        for (int q = 0; q < 4; q++) {
            const int row = (q >= 2) ? rowB : rowA;
            const int col = nt * 8 + tig * 2 + (q & 1);
            if (col >= NTOK) {
                accs[nt][q] = -1e30f;
            } else if (row < NTOK) {
                const int idx = (row / WSZ - col / WSZ + 6) * 13 + (row % WSZ - col % WSZ + 6);
                float a = accs[nt][q] + rpb_s[idx];
                if (rid_s[row] != rid_s[col]) a -= 100.0f;
                accs[nt][q] = a;
            }
        }
    }

    float mx0 = -1e30f, mx1 = -1e30f;
    #pragma unroll
    for (int nt = 0; nt < 8; nt++) {
        mx0 = fmaxf(mx0, fmaxf(accs[nt][0], accs[nt][1]));
        mx1 = fmaxf(mx1, fmaxf(accs[nt][2], accs[nt][3]));
    }
    #pragma unroll
    for (int o = 1; o < 4; o <<= 1) {
        mx0 = fmaxf(mx0, __shfl_xor_sync(0xffffffffu, mx0, o));
        mx1 = fmaxf(mx1, __shfl_xor_sync(0xffffffffu, mx1, o));
    }
    float s0 = 0.0f, s1 = 0.0f;
    #pragma unroll
    for (int nt = 0; nt < 8; nt++) {
        float e0 = __expf(accs[nt][0] - mx0); accs[nt][0] = e0; s0 += e0;
        float e1 = __expf(accs[nt][1] - mx0); accs[nt][1] = e1; s0 += e1;
        float e2 = __expf(accs[nt][2] - mx1); accs[nt][2] = e2; s1 += e2;
        float e3 = __expf(accs[nt][3] - mx1); accs[nt][3] = e3; s1 += e3;
    }
    #pragma unroll
    for (int o = 1; o < 4; o <<= 1) {
        s0 += __shfl_xor_sync(0xffffffffu, s0, o);
        s1 += __shfl_xor_sync(0xffffffffu, s1, o);
    }
    const float i0 = 1.0f / s0, i1 = 1.0f / s1;

    #pragma unroll
    for (int nt = 0; nt < 8; nt++) {
        const int col = nt * 8 + tig * 2;
        Ps[rowA][col]     = f2tf32(accs[nt][0] * i0);
        Ps[rowA][col + 1] = f2tf32(accs[nt][1] * i0);
        Ps[rowB][col]     = f2tf32(accs[nt][2] * i1);
        Ps[rowB][col + 1] = f2tf32(accs[nt][3] * i1);
    }
    __syncwarp();

    float acco[4][4];
    #pragma unroll
    for (int j = 0; j < 4; j++)
        #pragma unroll
        for (int q = 0; q < 4; q++) acco[j][q] = 0.0f;

    #pragma unroll
    for (int ks = 0; ks < 8; ++ks) {
        const int k0 = ks * 8;
        uint32_t af[4];
        af[0] = Ps[rowA][k0 + tig];
        af[1] = Ps[rowB][k0 + tig];
        af[2] = Ps[rowA][k0 + tig + 4];
        af[3] = Ps[rowB][k0 + tig + 4];
        #pragma unroll
        for (int nt = 0; nt < 4; nt++) {
            uint32_t bf[2] = { Vt[nt * 8 + gid][k0 + tig], Vt[nt * 8 + gid][k0 + tig + 4] };
            mma_tf32(acco[nt], af, bf);
        }
    }

    float* __restrict__ ob = g_att + (size_t)win * NTOK * CC + head * HDIM;
    #pragma unroll
    for (int h = 0; h < 2; h++) {
        const int row = r0 + gid + h * 8;
        if (row < NTOK) {
            #pragma unroll
            for (int nt = 0; nt < 4; nt++) {
                const int d = nt * 8 + tig * 2;
                float2 v = { rnd_tf32(acco[nt][h * 2]), rnd_tf32(acco[nt][h * 2 + 1]) };
                *(float2*)(ob + (size_t)row * CC + d) = v;
            }
        }
    }
}

// ================= launch =================
extern "C" void kernel_launch(void* const* d_in, const int* in_sizes, int n_in,
                              void* d_out, int out_size) {
    const float* rescaled = (const float*)d_in[0];
    const float* rescaler = (const float*)d_in[1];
    const float* gamma_a  = (const float*)d_in[2];
    const float* beta_a   = (const float*)d_in[3];
    const float* gamma_b  = (const float*)d_in[4];
    const float* beta_b   = (const float*)d_in[5];
    const float* Wqkv_a   = (const float*)d_in[6];
    const float* bqkv_a   = (const float*)d_in[7];
    const float* Wqkv_b   = (const float*)d_in[8];
    const float* bqkv_b   = (const float*)d_in[9];
    const float* rpb      = (const float*)d_in[10];
    const float* Wproj    = (const float*)d_in[11];
    const float* bproj    = (const float*)d_in[12];
    float* out = (float*)d_out;

    float *p_xw, *p_yw, *p_q, *p_k, *p_v, *p_att, *p_wt;
    cudaGetSymbolAddress((void**)&p_xw,  g_xw);
    cudaGetSymbolAddress((void**)&p_yw,  g_yw);
    cudaGetSymbolAddress((void**)&p_q,   g_q);
    cudaGetSymbolAddress((void**)&p_k,   g_k);
    cudaGetSymbolAddress((void**)&p_v,   g_v);
    cudaGetSymbolAddress((void**)&p_att, g_att);
    cudaGetSymbolAddress((void**)&p_wt,  g_wt);

    cudaFuncSetAttribute(gemm_tc, cudaFuncAttributeMaxDynamicSharedMemorySize, SMEM_DYN);

    ln_shift_window<<<dim3(BB * HH * WW, 2), 128>>>(rescaled, rescaler,
                                                    gamma_a, beta_a, gamma_b, beta_b);
    transpose_w<<<dim3(16, 16, 4), dim3(32, 8)>>>(Wqkv_a, Wqkv_b, Wproj);

    const dim3 ggrid(4, MROWS / 128);

    gemm_tc<<<ggrid, 256, SMEM_DYN>>>(p_yw, p_wt + 0 * 262144, bqkv_b,          SCALE, p_q, 0);
    gemm_tc<<<ggrid, 256, SMEM_DYN>>>(p_xw, p_wt + 1 * 262144, bqkv_a + CC,     1.0f,  p_k, 0);
    gemm_tc<<<ggrid, 256, SMEM_DYN>>>(p_xw, p_wt + 2 * 262144, bqkv_a + 2*CC,   1.0f,  p_v, 0);

    attn_mma<<<NWIN * NHEAD, 128>>>(rpb);

    gemm_tc<<<ggrid, 256, SMEM_DYN>>>(p_att, p_wt + 3 * 262144, bproj, 1.0f, out, 1);
}

// round 7
// speedup vs baseline: 4.5421x; 1.7720x over previous
#include <cuda_runtime.h>
#include <cuda_fp16.h>
#include <cstdint>

// ---------------- static config ----------------
#define BB    16
#define HH    56
#define WW    56
#define CC    512
#define WSZ   7
#define SHIFT 3
#define NHEAD 16
#define HDIM  32
#define NTOK  49
#define NWIN_PER_B 64
#define NWIN  (BB*NWIN_PER_B)        // 1024
#define MROWS (NWIN*NTOK)            // 50176
#define SCALE 0.17677669529663687f
#define LNEPS 1e-5f

// ---------------- scratch (fp16 intermediates) ----------------
__device__ __half g_xw[(size_t)MROWS * CC];
__device__ __half g_yw[(size_t)MROWS * CC];
__device__ __half g_q [(size_t)MROWS * CC];
__device__ __half g_k [(size_t)MROWS * CC];
__device__ __half g_v [(size_t)MROWS * CC];
__device__ __half g_att[(size_t)MROWS * CC];
__device__ __half g_wt[4 * 512 * 512];       // pre-transposed weights [n][k], fp16

__device__ __forceinline__ uint32_t packh2(float a, float b) {
    __half2 h = __floats2half2_rn(a, b);
    return *(uint32_t*)&h;
}
__device__ __forceinline__ void mma_f16(float* c, const uint32_t* a, const uint32_t* b) {
    asm volatile("mma.sync.aligned.m16n8k16.row.col.f32.f16.f16.f32 "
        "{%0,%1,%2,%3}, {%4,%5,%6,%7}, {%8,%9}, {%0,%1,%2,%3};"
        : "+f"(c[0]), "+f"(c[1]), "+f"(c[2]), "+f"(c[3])
        : "r"(a[0]), "r"(a[1]), "r"(a[2]), "r"(a[3]), "r"(b[0]), "r"(b[1]));
}
__device__ __forceinline__ uint32_t smem_u32(const void* p) {
    uint32_t a;
    asm("{ .reg .u64 t; cvta.to.shared.u64 t, %1; cvt.u32.u64 %0, t; }" : "=r"(a) : "l"(p));
    return a;
}
#define LDSM4(r, addr) \
    asm volatile("ldmatrix.sync.aligned.m8n8.x4.shared.b16 {%0,%1,%2,%3}, [%4];" \
        : "=r"((r)[0]), "=r"((r)[1]), "=r"((r)[2]), "=r"((r)[3]) : "r"(addr))
#define CP16(sa, gp) \
    asm volatile("cp.async.cg.shared.global [%0], [%1], 16;" :: "r"(sa), "l"(gp))
#define CP_COMMIT() asm volatile("cp.async.commit_group;" ::: "memory")

// ================= Kernel 1: LayerNorm + roll(-3,-3) + window partition -> fp16 ==========
__global__ void ln_shift_window(const float* __restrict__ xa, const float* __restrict__ xb,
                                const float* __restrict__ ga, const float* __restrict__ ba,
                                const float* __restrict__ gb, const float* __restrict__ bb) {
    const int pix = blockIdx.x;
    const int sel = blockIdx.y;
    const float* __restrict__ x  = sel ? xb : xa;
    const float* __restrict__ g  = sel ? gb : ga;
    const float* __restrict__ be = sel ? bb : ba;
    __half* __restrict__ out     = sel ? g_yw : g_xw;

    const int t = threadIdx.x;
    const float4 v = ((const float4*)(x + (size_t)pix * CC))[t];

    float s  = v.x + v.y + v.z + v.w;
    float sq = v.x*v.x + v.y*v.y + v.z*v.z + v.w*v.w;
    #pragma unroll
    for (int o = 16; o > 0; o >>= 1) {
        s  += __shfl_down_sync(0xffffffffu, s,  o);
        sq += __shfl_down_sync(0xffffffffu, sq, o);
    }
    __shared__ float red[8];
    const int warp = t >> 5, lane = t & 31;
    if (lane == 0) { red[warp] = s; red[warp + 4] = sq; }
    __syncthreads();
    s  = red[0] + red[1] + red[2] + red[3];
    sq = red[4] + red[5] + red[6] + red[7];

    const float mean = s * (1.0f / CC);
    const float var  = sq * (1.0f / CC) - mean * mean;
    const float inv  = rsqrtf(var + LNEPS);

    const float4 gg = ((const float4*)g)[t];
    const float4 bt = ((const float4*)be)[t];
    const float ox = (v.x - mean) * inv * gg.x + bt.x;
    const float oy = (v.y - mean) * inv * gg.y + bt.y;
    const float oz = (v.z - mean) * inv * gg.z + bt.z;
    const float ow = (v.w - mean) * inv * gg.w + bt.w;

    const int b   = pix / (HH * WW);
    const int rem = pix % (HH * WW);
    const int h   = rem / WW, w = rem % WW;
    int hr = h - SHIFT; if (hr < 0) hr += HH;
    int wr = w - SHIFT; if (wr < 0) wr += WW;
    const int win = b * NWIN_PER_B + (hr / WSZ) * 8 + (wr / WSZ);
    const int n   = (hr % WSZ) * WSZ + (wr % WSZ);
    uint32_t* orow = (uint32_t*)(out + ((size_t)(win * NTOK + n)) * CC);
    orow[2 * t]     = packh2(ox, oy);
    orow[2 * t + 1] = packh2(oz, ow);
}

// ================= Kernel 2: weight transpose (W[k][n] -> WT[n][k]) -> fp16 ==============
__global__ void transpose_w(const float* __restrict__ Wqa, const float* __restrict__ Wqb,
                            const float* __restrict__ Wp) {
    __shared__ float tile[32][33];
    const int m = blockIdx.z;
    const float* src; int ld, off;
    if      (m == 0) { src = Wqb; ld = 1536; off = 0;    }
    else if (m == 1) { src = Wqa; ld = 1536; off = 512;  }
    else if (m == 2) { src = Wqa; ld = 1536; off = 1024; }
    else             { src = Wp;  ld = 512;  off = 0;    }
    __half* dst = g_wt + (size_t)m * 512 * 512;
    const int n0 = blockIdx.x * 32, k0 = blockIdx.y * 32;
    const int tx = threadIdx.x, ty = threadIdx.y;
    #pragma unroll
    for (int i = 0; i < 32; i += 8)
        tile[ty + i][tx] = src[(size_t)(k0 + ty + i) * ld + off + n0 + tx];
    __syncthreads();
    #pragma unroll
    for (int i = 0; i < 32; i += 8)
        dst[(size_t)(n0 + ty + i) * 512 + k0 + tx] = __float2half_rn(tile[tx][ty + i]);
}

// ================= Kernel 3: fp16 mma.sync GEMM, cp.async 4-stage + ldmatrix =============
// SMEM row: 32 fp16 k-elements = 64B data + 16B pad = 80B (conflict-free for LDSM phases)
#define ROW_B  80
#define STG_B  (128 * ROW_B)                   // 10240 bytes per tensor per stage
#define NSTG   4
#define SMEM_DYN (NSTG * 2 * STG_B)            // 81920

__global__ __launch_bounds__(256, 2)
void gemm_tc(const __half* __restrict__ A, const __half* __restrict__ WT,
             const float* __restrict__ bias, float scale,
             void* __restrict__ outv, int mode) {
    extern __shared__ uint32_t smem[];

    const int bm   = blockIdx.y * 128;
    const int bn   = blockIdx.x * 128;
    const int t    = threadIdx.x;
    const int wid  = t >> 5;
    const int lane = t & 31;
    const int gid  = lane >> 2;
    const int tig  = lane & 3;
    const int wm   = wid & 3;
    const int wn   = wid >> 2;

    const uint32_t sBase = smem_u32(smem);
    const uint32_t bBase = sBase + NSTG * STG_B;

    // cp.async: row r = t>>1, 32B chunk = (t&1)
    const int r  = t >> 1;
    const int ch = t & 1;
    const __half* __restrict__ Ap = A  + (size_t)(bm + r) * 512 + ch * 16;
    const __half* __restrict__ Bp = WT + (size_t)(bn + r) * 512 + ch * 16;
    const uint32_t stsByte = (uint32_t)(r * ROW_B + ch * 32);

    #define PREFETCH(kt, st) do { \
        const uint32_t aDst = sBase + (st) * STG_B + stsByte; \
        const uint32_t bDst = bBase + (st) * STG_B + stsByte; \
        const __half* Aq = Ap + (kt) * 32; \
        const __half* Bq = Bp + (kt) * 32; \
        CP16(aDst,      Aq);     CP16(aDst + 16, Aq + 8); \
        CP16(bDst,      Bq);     CP16(bDst + 16, Bq + 8); \
        CP_COMMIT(); } while (0)

    // ldmatrix lane offsets: quadrants m0(+0,+0) m1(+8rows,+0) m2(+0,+16B) m3(+8rows,+16B)
    const int mat  = lane >> 3;
    const int rInM = lane & 7;
    const uint32_t aOffL = (uint32_t)((wm * 32 + rInM + (mat & 1) * 8) * ROW_B
                                      + (mat >> 1) * 16);
    const uint32_t bOffL = (uint32_t)((wn * 64 + rInM + (mat & 1) * 8) * ROW_B
                                      + (mat >> 1) * 16);

    float acc[2][8][4];
    #pragma unroll
    for (int i = 0; i < 2; i++)
        #pragma unroll
        for (int j = 0; j < 8; j++)
            #pragma unroll
            for (int q = 0; q < 4; q++) acc[i][j][q] = 0.0f;

    PREFETCH(0, 0);
    PREFETCH(1, 1);
    PREFETCH(2, 2);

    for (int kt = 0; kt < 16; ++kt) {
        if (kt <= 13)      asm volatile("cp.async.wait_group 2;" ::: "memory");
        else if (kt == 14) asm volatile("cp.async.wait_group 1;" ::: "memory");
        else               asm volatile("cp.async.wait_group 0;" ::: "memory");
        __syncthreads();
        if (kt + 3 < 16) PREFETCH(kt + 3, (kt + 3) & 3);   // stage (kt-1)&3: readers past barrier

        const int st = kt & 3;
        const uint32_t aB = sBase + st * STG_B + aOffL;
        const uint32_t bB = bBase + st * STG_B + bOffL;
        #pragma unroll
        for (int ks = 0; ks < 2; ++ks) {
            const uint32_t kb = ks * 32;                   // 16 halves
            uint32_t a0[4], a1[4];
            LDSM4(a0, aB + kb);
            LDSM4(a1, aB + 16 * ROW_B + kb);
            #pragma unroll
            for (int jp = 0; jp < 4; ++jp) {
                uint32_t bq[4];
                LDSM4(bq, bB + jp * 16 * ROW_B + kb);
                // bq: r0=(n0-7,k0-7) r1=(n8-15,k0-7) r2=(n0-7,k8-15) r3=(n8-15,k8-15)
                uint32_t b0[2] = { bq[0], bq[2] };
                uint32_t b1[2] = { bq[1], bq[3] };
                mma_f16(acc[0][2*jp],     a0, b0);
                mma_f16(acc[0][2*jp + 1], a0, b1);
                mma_f16(acc[1][2*jp],     a1, b0);
                mma_f16(acc[1][2*jp + 1], a1, b1);
            }
        }
    }
    #undef PREFETCH

    // ---- epilogue ----
    const int row0 = bm + wm * 32;
    const int cw0  = bn + wn * 64;
    #pragma unroll
    for (int i = 0; i < 2; i++) {
        #pragma unroll
        for (int half = 0; half < 2; half++) {
            const int row = row0 + i * 16 + gid + half * 8;
            const int win = row / NTOK;
            const int n   = row % NTOK;
            if (mode == 0) {
                __half* rowbase = (__half*)outv + ((size_t)win * NHEAD * NTOK + n) * HDIM;
                #pragma unroll
                for (int j = 0; j < 8; j++) {
                    const int c = cw0 + j * 8 + tig * 2;
                    const float2 bs = *(const float2*)(bias + c);
                    const float vx = (acc[i][j][half * 2 + 0] + bs.x) * scale;
                    const float vy = (acc[i][j][half * 2 + 1] + bs.y) * scale;
                    const int head = c >> 5, d = c & 31;
                    *(uint32_t*)(rowbase + (size_t)head * NTOK * HDIM + d) = packh2(vx, vy);
                }
            } else {
                const int b  = win >> 6;
                const int lw = win & 63;
                const int hr = (lw >> 3) * WSZ + n / WSZ;
                const int wr = (lw & 7)  * WSZ + n % WSZ;
                int h = hr + SHIFT; if (h >= HH) h -= HH;
                int w = wr + SHIFT; if (w >= WW) w -= WW;
                float* rowbase = (float*)outv + ((size_t)b * (HH * WW) + h * WW + w) * CC;
                #pragma unroll
                for (int j = 0; j < 8; j++) {
                    const int c = cw0 + j * 8 + tig * 2;
                    const float2 bs = *(const float2*)(bias + c);
                    float2 v;
                    v.x = (acc[i][j][half * 2 + 0] + bs.x) * scale;
                    v.y = (acc[i][j][half * 2 + 1] + bs.y) * scale;
                    *(float2*)(rowbase + c) = v;
                }
            }
        }
    }
}

// ================= Kernel 4: fp16 tensor-core windowed attention =================
__global__ __launch_bounds__(128)
void attn_mma(const float* __restrict__ rpb_table) {
    const int unit = blockIdx.x;
    const int win  = unit >> 4;
    const int head = unit & 15;
    const int nw   = win & (NWIN_PER_B - 1);

    __shared__ uint32_t Qs[64][20];   // half2 [n][kk], kk 0..15 used
    __shared__ uint32_t Ks[64][20];
    __shared__ uint32_t Vt[32][36];   // half2 [d][jm], jm = m/2, 0..31 used
    __shared__ uint32_t Ps[64][36];   // half2 [n][jm]
    __shared__ float rpb_s[169];
    __shared__ int   rid_s[NTOK];

    const int t    = threadIdx.x;
    const int wid  = t >> 5;
    const int lane = t & 31;
    const int gid  = lane >> 2;
    const int tig  = lane & 3;
    const int r0   = wid * 16;

    const uint32_t* __restrict__ qb2 = (const uint32_t*)(g_q + (size_t)unit * NTOK * HDIM);
    const uint32_t* __restrict__ kb2 = (const uint32_t*)(g_k + (size_t)unit * NTOK * HDIM);
    const __half*   __restrict__ vh  = g_v + (size_t)unit * NTOK * HDIM;

    for (int e = t; e < 64 * 16; e += 128) {
        const int n = e >> 4, kk = e & 15;
        const bool ok = n < NTOK;
        Qs[n][kk] = ok ? qb2[n * 16 + kk] : 0u;
        Ks[n][kk] = ok ? kb2[n * 16 + kk] : 0u;
    }
    for (int e = t; e < 32 * 32; e += 128) {
        const int d = e >> 5, j = e & 31;
        const int m0 = 2 * j, m1 = 2 * j + 1;
        const float f0 = (m0 < NTOK) ? __half2float(vh[m0 * HDIM + d]) : 0.0f;
        const float f1 = (m1 < NTOK) ? __half2float(vh[m1 * HDIM + d]) : 0.0f;
        Vt[d][j] = packh2(f0, f1);
    }
    for (int e = t; e < 169; e += 128) rpb_s[e] = rpb_table[e * NHEAD + head];
    if (t < NTOK) {
        const int i = t / WSZ, j = t % WSZ;
        const int h = (nw >> 3) * WSZ + i;
        const int w = (nw & 7)  * WSZ + j;
        const int rh = (h < HH - WSZ) ? 0 : ((h < HH - SHIFT) ? 1 : 2);
        const int rw = (w < WW - WSZ) ? 0 : ((w < WW - SHIFT) ? 1 : 2);
        rid_s[t] = rh * 3 + rw;
    }
    __syncthreads();

    const int rowA = r0 + gid;
    const int rowB = r0 + gid + 8;

    // ---- QK^T (m16n8k16, 2 k-steps over HDIM=32) ----
    float accs[8][4];
    #pragma unroll
    for (int j = 0; j < 8; j++)
        #pragma unroll
        for (int q = 0; q < 4; q++) accs[j][q] = 0.0f;

    #pragma unroll
    for (int ks = 0; ks < 2; ++ks) {
        const int k0h = ks * 8;     // half2 units
        uint32_t af[4];
        af[0] = Qs[rowA][k0h + tig];
        af[1] = Qs[rowB][k0h + tig];
        af[2] = Qs[rowA][k0h + 4 + tig];
        af[3] = Qs[rowB][k0h + 4 + tig];
        #pragma unroll
        for (int nt = 0; nt < 8; nt++) {
            uint32_t bf[2] = { Ks[nt * 8 + gid][k0h + tig], Ks[nt * 8 + gid][k0h + 4 + tig] };
            mma_f16(accs[nt], af, bf);
        }
    }

    // ---- rpb + shift-mask ----
    #pragma unroll
    for (int nt = 0; nt < 8; nt++) {
        #pragma unroll
        for (int q = 0; q < 4; q++) {
            const int row = (q >= 2) ? rowB : rowA;
            const int col = nt * 8 + tig * 2 + (q & 1);
            if (col >= NTOK) {
                accs[nt][q] = -1e30f;
            } else if (row < NTOK) {
                const int idx = (row / WSZ - col / WSZ + 6) * 13 + (row % WSZ - col % WSZ + 6);
                float a = accs[nt][q] + rpb_s[idx];
                if (rid_s[row] != rid_s[col]) a -= 100.0f;
                accs[nt][q] = a;
            }
        }
    }

    // ---- softmax ----
    float mx0 = -1e30f, mx1 = -1e30f;
    #pragma unroll
    for (int nt = 0; nt < 8; nt++) {
        mx0 = fmaxf(mx0, fmaxf(accs[nt][0], accs[nt][1]));
        mx1 = fmaxf(mx1, fmaxf(accs[nt][2], accs[nt][3]));
    }
    #pragma unroll
    for (int o = 1; o < 4; o <<= 1) {
        mx0 = fmaxf(mx0, __shfl_xor_sync(0xffffffffu, mx0, o));
        mx1 = fmaxf(mx1, __shfl_xor_sync(0xffffffffu, mx1, o));
    }
    float s0 = 0.0f, s1 = 0.0f;
    #pragma unroll
    for (int nt = 0; nt < 8; nt++) {
        float e0 = __expf(accs[nt][0] - mx0); accs[nt][0] = e0; s0 += e0;
        float e1 = __expf(accs[nt][1] - mx0); accs[nt][1] = e1; s0 += e1;
        float e2 = __expf(accs[nt][2] - mx1); accs[nt][2] = e2; s1 += e2;
        float e3 = __expf(accs[nt][3] - mx1); accs[nt][3] = e3; s1 += e3;
    }
    #pragma unroll
    for (int o = 1; o < 4; o <<= 1) {
        s0 += __shfl_xor_sync(0xffffffffu, s0, o);
        s1 += __shfl_xor_sync(0xffffffffu, s1, o);
    }
    const float i0 = 1.0f / s0, i1 = 1.0f / s1;

    // ---- P -> smem (half2) ----
    #pragma unroll
    for (int nt = 0; nt < 8; nt++) {
        Ps[rowA][nt * 4 + tig] = packh2(accs[nt][0] * i0, accs[nt][1] * i0);
        Ps[rowB][nt * 4 + tig] = packh2(accs[nt][2] * i1, accs[nt][3] * i1);
    }
    __syncwarp();

    // ---- PV (k over 64 tokens = 4 k-steps) ----
    float acco[4][4];
    #pragma unroll
    for (int j = 0; j < 4; j++)
        #pragma unroll
        for (int q = 0; q < 4; q++) acco[j][q] = 0.0f;

    #pragma unroll
    for (int ks = 0; ks < 4; ++ks) {
        const int k0h = ks * 8;
        uint32_t af[4];
        af[0] = Ps[rowA][k0h + tig];
        af[1] = Ps[rowB][k0h + tig];
        af[2] = Ps[rowA][k0h + 4 + tig];
        af[3] = Ps[rowB][k0h + 4 + tig];
        #pragma unroll
        for (int nt = 0; nt < 4; nt++) {
            uint32_t bf[2] = { Vt[nt * 8 + gid][k0h + tig], Vt[nt * 8 + gid][k0h + 4 + tig] };
            mma_f16(acco[nt], af, bf);
        }
    }

    // ---- store output (fp16) ----
    __half* __restrict__ ob = g_att + (size_t)win * NTOK * CC + head * HDIM;
    #pragma unroll
    for (int h = 0; h < 2; h++) {
        const int row = r0 + gid + h * 8;
        if (row < NTOK) {
            #pragma unroll
            for (int nt = 0; nt < 4; nt++) {
                const int d = nt * 8 + tig * 2;
                *(uint32_t*)(ob + (size_t)row * CC + d) = packh2(acco[nt][h * 2], acco[nt][h * 2 + 1]);
            }
        }
    }
}

// ================= launch =================
extern "C" void kernel_launch(void* const* d_in, const int* in_sizes, int n_in,
                              void* d_out, int out_size) {
    const float* rescaled = (const float*)d_in[0];
    const float* rescaler = (const float*)d_in[1];
    const float* gamma_a  = (const float*)d_in[2];
    const float* beta_a   = (const float*)d_in[3];
    const float* gamma_b  = (const float*)d_in[4];
    const float* beta_b   = (const float*)d_in[5];
    const float* Wqkv_a   = (const float*)d_in[6];
    const float* bqkv_a   = (const float*)d_in[7];
    const float* Wqkv_b   = (const float*)d_in[8];
    const float* bqkv_b   = (const float*)d_in[9];
    const float* rpb      = (const float*)d_in[10];
    const float* Wproj    = (const float*)d_in[11];
    const float* bproj    = (const float*)d_in[12];
    float* out = (float*)d_out;

    __half *p_xw, *p_yw, *p_q, *p_k, *p_v, *p_att, *p_wt;
    cudaGetSymbolAddress((void**)&p_xw,  g_xw);
    cudaGetSymbolAddress((void**)&p_yw,  g_yw);
    cudaGetSymbolAddress((void**)&p_q,   g_q);
    cudaGetSymbolAddress((void**)&p_k,   g_k);
    cudaGetSymbolAddress((void**)&p_v,   g_v);
    cudaGetSymbolAddress((void**)&p_att, g_att);
    cudaGetSymbolAddress((void**)&p_wt,  g_wt);

    cudaFuncSetAttribute(gemm_tc, cudaFuncAttributeMaxDynamicSharedMemorySize, SMEM_DYN);

    ln_shift_window<<<dim3(BB * HH * WW, 2), 128>>>(rescaled, rescaler,
                                                    gamma_a, beta_a, gamma_b, beta_b);
    transpose_w<<<dim3(16, 16, 4), dim3(32, 8)>>>(Wqkv_a, Wqkv_b, Wproj);

    const dim3 ggrid(4, MROWS / 128);

    gemm_tc<<<ggrid, 256, SMEM_DYN>>>(p_yw, p_wt + 0 * 262144, bqkv_b,          SCALE, p_q, 0);
    gemm_tc<<<ggrid, 256, SMEM_DYN>>>(p_xw, p_wt + 1 * 262144, bqkv_a + CC,     1.0f,  p_k, 0);
    gemm_tc<<<ggrid, 256, SMEM_DYN>>>(p_xw, p_wt + 2 * 262144, bqkv_a + 2*CC,   1.0f,  p_v, 0);

    attn_mma<<<NWIN * NHEAD, 128>>>(rpb);

    gemm_tc<<<ggrid, 256, SMEM_DYN>>>(p_att, p_wt + 3 * 262144, bproj, 1.0f, out, 1);
}